// round 12
// baseline (speedup 1.0000x reference)
#include <cuda_runtime.h>
#include <math.h>

#define N_NODES 50000
#define N_EDGES 800000
#define F_NODE  92
#define F_EDGE  50
#define HID     128

// ---------------- scratch (static device globals) ---------------------------
__device__ float g_h[N_NODES * HID];
__device__ float g_Apack[N_NODES * 4 * HID];    // [node][512]: Afi|Afj|Asi|Asj
__device__ float g_agg[N_NODES * HID];
__device__ float g_Wpack[2 * HID * 4 * HID];    // packed proj weights [l][128][512]

// ---------------- tf32 helpers ----------------------------------------------
__device__ __forceinline__ unsigned f2tf32(float f) {
    unsigned u;
    asm("cvt.rna.tf32.f32 %0, %1;" : "=r"(u) : "f"(f));
    return u;
}

__device__ __forceinline__ void mma_tf32(float& d0, float& d1, float& d2, float& d3,
                                         unsigned a0, unsigned a1, unsigned a2, unsigned a3,
                                         unsigned b0, unsigned b1)
{
    asm volatile(
        "mma.sync.aligned.m16n8k8.row.col.f32.tf32.tf32.f32 "
        "{%0,%1,%2,%3}, {%4,%5,%6,%7}, {%8,%9}, {%0,%1,%2,%3};"
        : "+f"(d0), "+f"(d1), "+f"(d2), "+f"(d3)
        : "r"(a0), "r"(a1), "r"(a2), "r"(a3), "r"(b0), "r"(b1));
}

// ---------------- packed f32x2 helpers (Blackwell FFMA2) ----------------------
#define FMA_F32X2(d, a, b, c) \
    asm("fma.rn.f32x2 %0, %1, %2, %3;" : "=l"(d) : "l"(a), "l"(b), "l"(c))
#define PACK_F32X2(out, lo, hi) \
    asm("mov.b64 %0, {%1, %2};" : "=l"(out) : "r"(lo), "r"(hi))
#define UNPACK_F32X2(lo, hi, in) \
    asm("mov.b64 {%0, %1}, %2;" : "=r"(lo), "=r"(hi) : "l"(in))

// vectorized global reduction
#define RED_ADD_V4F32(ptr, v0, v1, v2, v3) \
    asm volatile("red.global.add.v4.f32 [%0], {%1, %2, %3, %4};" \
                 :: "l"(ptr), "f"(v0), "f"(v1), "f"(v2), "f"(v3) : "memory")

// cp.async 16B with zero-fill predicate (src_bytes = 16 or 0)
__device__ __forceinline__ void cp_async16(void* smem_ptr, const void* gmem_ptr, int src_bytes) {
    unsigned saddr = (unsigned)__cvta_generic_to_shared(smem_ptr);
    asm volatile("cp.async.ca.shared.global [%0], [%1], 16, %2;"
                 :: "r"(saddr), "l"(gmem_ptr), "r"(src_bytes));
}
#define CP_ASYNC_COMMIT() asm volatile("cp.async.commit_group;")
#define CP_ASYNC_WAIT1()  asm volatile("cp.async.wait_group 1;")
#define CP_ASYNC_WAIT0()  asm volatile("cp.async.wait_group 0;")

// fast message math: sigmoid(pf) * softplus(ps), MUFU-based
__device__ __forceinline__ float msg_fast(float pf, float ps) {
    float sig = __fdividef(1.f, 1.f + __expf(-pf));
    float sp  = fmaxf(ps, 0.f) + __logf(1.f + __expf(-fabsf(ps)));
    return sig * sp;
}

// ---------------- tf32 GEMM, 2-stage cp.async pipeline, dual-store ------------
// C = act(A[M,K] @ B[K,N] (+bias)); optional second destination C2 (same data).
#define GBM 128
#define GBN 128
#define GBK 32
#define ASTR 36
#define BSTR 136
#define GEMM_SMEM ((2 * GBM * ASTR + 2 * GBK * BSTR) * 4)   // 71680 B

template<int ACT>  // 0 = none, 1 = relu
__global__ __launch_bounds__(256)
void gemm_tf32_kernel(const float* __restrict__ A, const float* __restrict__ B,
                      const float* __restrict__ bias, float* __restrict__ C,
                      float* __restrict__ C2,
                      int M, int N, int K)
{
    extern __shared__ float smem[];
    float* Asm = smem;                       // [2][GBM][ASTR]
    float* Bsm = smem + 2 * GBM * ASTR;      // [2][GBK][BSTR]

    const int tid  = threadIdx.x;
    const int lane = tid & 31;
    const int warp = tid >> 5;
    const int g    = lane >> 2;
    const int t    = lane & 3;

    const int row0 = blockIdx.y * GBM;
    const int col0 = blockIdx.x * GBN;
    const int wr0  = (warp >> 1) * 32;
    const int wc0  = (warp & 1) * 64;

    const int KT = (K + GBK - 1) / GBK;

    auto issue_tile = [&](int stage, int k0) {
        float* as = Asm + stage * GBM * ASTR;
        float* bs = Bsm + stage * GBK * BSTR;
#pragma unroll
        for (int i = 0; i < 4; i++) {
            int id = tid + i * 256;
            int r  = id >> 3;
            int cc = id & 7;
            int gr = row0 + r;
            int gc = k0 + cc * 4;
            int bytes = (gr < M && gc < K) ? 16 : 0;
            const float* src = bytes ? (A + (long long)gr * K + gc) : A;
            cp_async16(as + r * ASTR + cc * 4, src, bytes);
        }
#pragma unroll
        for (int i = 0; i < 4; i++) {
            int id = tid + i * 256;
            int r  = id >> 5;
            int cc = id & 31;
            int gr = k0 + r;
            int gc = col0 + cc * 4;
            int bytes = (gr < K && gc < N) ? 16 : 0;
            const float* src = bytes ? (B + (long long)gr * N + gc) : B;
            cp_async16(bs + r * BSTR + cc * 4, src, bytes);
        }
        CP_ASYNC_COMMIT();
    };

    float acc[2][8][4];
#pragma unroll
    for (int m = 0; m < 2; m++)
#pragma unroll
        for (int n = 0; n < 8; n++)
#pragma unroll
            for (int i = 0; i < 4; i++) acc[m][n][i] = 0.f;

    issue_tile(0, 0);

    for (int it = 0; it < KT; it++) {
        const int cur = it & 1;
        if (it + 1 < KT) {
            issue_tile((it + 1) & 1, (it + 1) * GBK);
            CP_ASYNC_WAIT1();
        } else {
            CP_ASYNC_WAIT0();
        }
        __syncthreads();

        const float* as = Asm + cur * GBM * ASTR;
        const float* bs = Bsm + cur * GBK * BSTR;

#pragma unroll
        for (int kk = 0; kk < GBK / 8; kk++) {
            const int kb = kk * 8;
            unsigned a[2][4];
#pragma unroll
            for (int m = 0; m < 2; m++) {
                int r = wr0 + m * 16;
                a[m][0] = f2tf32(as[(r + g    ) * ASTR + kb + t    ]);
                a[m][1] = f2tf32(as[(r + g + 8) * ASTR + kb + t    ]);
                a[m][2] = f2tf32(as[(r + g    ) * ASTR + kb + t + 4]);
                a[m][3] = f2tf32(as[(r + g + 8) * ASTR + kb + t + 4]);
            }
#pragma unroll
            for (int n = 0; n < 8; n++) {
                int c = wc0 + n * 8 + g;
                unsigned b0 = f2tf32(bs[(kb + t    ) * BSTR + c]);
                unsigned b1 = f2tf32(bs[(kb + t + 4) * BSTR + c]);
#pragma unroll
                for (int m = 0; m < 2; m++)
                    mma_tf32(acc[m][n][0], acc[m][n][1], acc[m][n][2], acc[m][n][3],
                             a[m][0], a[m][1], a[m][2], a[m][3], b0, b1);
            }
        }
        __syncthreads();
    }

#pragma unroll
    for (int m = 0; m < 2; m++) {
#pragma unroll
        for (int n = 0; n < 8; n++) {
            int gc = col0 + wc0 + n * 8 + 2 * t;
            float bx = 0.f, by = 0.f;
            if (bias) { bx = bias[gc]; by = bias[gc + 1]; }

            int gr0 = row0 + wr0 + m * 16 + g;
            if (gr0 < M) {
                float v0 = acc[m][n][0] + bx;
                float v1 = acc[m][n][1] + by;
                if (ACT == 1) { v0 = fmaxf(v0, 0.f); v1 = fmaxf(v1, 0.f); }
                float2 v = make_float2(v0, v1);
                *reinterpret_cast<float2*>(&C[(long long)gr0 * N + gc]) = v;
                if (C2) *reinterpret_cast<float2*>(&C2[(long long)gr0 * N + gc]) = v;
            }
            int gr1 = gr0 + 8;
            if (gr1 < M) {
                float v0 = acc[m][n][2] + bx;
                float v1 = acc[m][n][3] + by;
                if (ACT == 1) { v0 = fmaxf(v0, 0.f); v1 = fmaxf(v1, 0.f); }
                float2 v = make_float2(v0, v1);
                *reinterpret_cast<float2*>(&C[(long long)gr1 * N + gc]) = v;
                if (C2) *reinterpret_cast<float2*>(&C2[(long long)gr1 * N + gc]) = v;
            }
        }
    }
}

// ---------------- weight pack -------------------------------------------------
__global__ void pack_weights_kernel(const float* __restrict__ Wf,
                                    const float* __restrict__ Ws,
                                    float* __restrict__ Wpack)
{
    int idx = blockIdx.x * 256 + threadIdx.x;
    if (idx >= 2 * 128 * 512) return;
    int l = idx >> 16;
    int k = (idx >> 9) & 127;
    int c = idx & 511;
    int sel = c >> 7;
    int j = c & 127;
    const float* W = (sel < 2) ? Wf : Ws;
    int row = (sel & 1) ? (128 + k) : k;
    Wpack[idx] = W[(long long)l * 306 * 128 + row * 128 + j];
}

// ---------------- fused edge kernel (8-edge ILP, FFMA2, dup-ea smem) ----------
#define TE 128
// smem: Wf 6400 f + Ws 6400 f + ea2 (TE*50 float2) = 102400 B
#define EDGE_SMEM (6400 * 4 + 6400 * 4 + TE * F_EDGE * 8)

__global__ __launch_bounds__(256, 2)
void edge_fused_kernel(const float* __restrict__ edge_attr,
                       const float* __restrict__ Wfe,   // [50][128]
                       const float* __restrict__ Wse,   // [50][128]
                       const float* __restrict__ bf_l,
                       const float* __restrict__ bs_l,
                       const float* __restrict__ Apack, // [N_NODES][512]
                       const int* __restrict__ src_idx,
                       const int* __restrict__ dst_idx,
                       float* __restrict__ agg)
{
    extern __shared__ float sm[];
    float* Wf_s = sm;                  // 6400 floats
    float* Ws_s = sm + 6400;           // 6400 floats
    float2* ea2 = reinterpret_cast<float2*>(sm + 12800);   // [TE*50] duplicated
    const unsigned long long* ea64 = reinterpret_cast<const unsigned long long*>(ea2);

    const int tid  = threadIdx.x;
    const int lane = tid & 31;
    const int warp = tid >> 5;
    const int e0   = blockIdx.x * TE;

    // load weights (float4, coalesced)
    {
        const float4* wf4 = reinterpret_cast<const float4*>(Wfe);
        const float4* ws4 = reinterpret_cast<const float4*>(Wse);
        float4* sf4 = reinterpret_cast<float4*>(Wf_s);
        float4* ss4 = reinterpret_cast<float4*>(Ws_s);
#pragma unroll
        for (int i = 0; i < 7; i++) {
            int idx = tid + i * 256;
            if (idx < 1600) { sf4[idx] = wf4[idx]; ss4[idx] = ws4[idx]; }
        }
    }
    // load edge_attr tile, duplicated into f32x2 pairs
    {
        const float* gbase = edge_attr + (long long)e0 * F_EDGE;
#pragma unroll
        for (int i = 0; i < (TE * F_EDGE) / 256; i++) {
            int idx = tid + i * 256;
            float v = gbase[idx];
            ea2[idx] = make_float2(v, v);
        }
    }
    __syncthreads();

    const float4 bf4 = *reinterpret_cast<const float4*>(bf_l + lane * 4);
    const float4 bs4 = *reinterpret_cast<const float4*>(bs_l + lane * 4);
    unsigned long long bf01, bf23, bs01, bs23;
    PACK_F32X2(bf01, __float_as_uint(bf4.x), __float_as_uint(bf4.y));
    PACK_F32X2(bf23, __float_as_uint(bf4.z), __float_as_uint(bf4.w));
    PACK_F32X2(bs01, __float_as_uint(bs4.x), __float_as_uint(bs4.y));
    PACK_F32X2(bs23, __float_as_uint(bs4.z), __float_as_uint(bs4.w));

    // each warp handles 16 edges, 8 at a time
#pragma unroll 1
    for (int grp = 0; grp < 2; grp++) {
        const int elb = warp * 16 + grp * 8;

        unsigned long long af01[8], af23[8], as01[8], as23[8];
#pragma unroll
        for (int q = 0; q < 8; q++) {
            af01[q] = bf01; af23[q] = bf23;
            as01[q] = bs01; as23[q] = bs23;
        }

#pragma unroll 1
        for (int k = 0; k < F_EDGE; k += 2) {
            const ulonglong2 wf0 = *reinterpret_cast<const ulonglong2*>(&Wf_s[k * 128 + lane * 4]);
            const ulonglong2 ws0 = *reinterpret_cast<const ulonglong2*>(&Ws_s[k * 128 + lane * 4]);
            const ulonglong2 wf1 = *reinterpret_cast<const ulonglong2*>(&Wf_s[(k + 1) * 128 + lane * 4]);
            const ulonglong2 ws1 = *reinterpret_cast<const ulonglong2*>(&Ws_s[(k + 1) * 128 + lane * 4]);

#pragma unroll
            for (int q = 0; q < 8; q++) {
                // LDS.64 broadcast of pre-duplicated {v,v} pairs — no pack movs
                const unsigned long long alo = ea64[(elb + q) * F_EDGE + k];
                const unsigned long long ahi = ea64[(elb + q) * F_EDGE + k + 1];

                FMA_F32X2(af01[q], alo, wf0.x, af01[q]);
                FMA_F32X2(af23[q], alo, wf0.y, af23[q]);
                FMA_F32X2(as01[q], alo, ws0.x, as01[q]);
                FMA_F32X2(as23[q], alo, ws0.y, as23[q]);
                FMA_F32X2(af01[q], ahi, wf1.x, af01[q]);
                FMA_F32X2(af23[q], ahi, wf1.y, af23[q]);
                FMA_F32X2(as01[q], ahi, ws1.x, as01[q]);
                FMA_F32X2(as23[q], ahi, ws1.y, as23[q]);
            }
        }

#pragma unroll
        for (int q = 0; q < 8; q++) {
            const int e = e0 + elb + q;
            const int s = src_idx[e];
            const int d = dst_idx[e];

            unsigned f0u, f1u, f2u, f3u, s0u, s1u, s2u, s3u;
            UNPACK_F32X2(f0u, f1u, af01[q]);
            UNPACK_F32X2(f2u, f3u, af23[q]);
            UNPACK_F32X2(s0u, s1u, as01[q]);
            UNPACK_F32X2(s2u, s3u, as23[q]);

            const float4 afi = *reinterpret_cast<const float4*>(&Apack[(long long)d * 512 + lane * 4]);
            const float4 afj = *reinterpret_cast<const float4*>(&Apack[(long long)s * 512 + 128 + lane * 4]);
            const float4 asi = *reinterpret_cast<const float4*>(&Apack[(long long)d * 512 + 256 + lane * 4]);
            const float4 asj = *reinterpret_cast<const float4*>(&Apack[(long long)s * 512 + 384 + lane * 4]);

            float pf0 = __uint_as_float(f0u) + afi.x + afj.x;
            float pf1 = __uint_as_float(f1u) + afi.y + afj.y;
            float pf2 = __uint_as_float(f2u) + afi.z + afj.z;
            float pf3 = __uint_as_float(f3u) + afi.w + afj.w;
            float ps0 = __uint_as_float(s0u) + asi.x + asj.x;
            float ps1 = __uint_as_float(s1u) + asi.y + asj.y;
            float ps2 = __uint_as_float(s2u) + asi.z + asj.z;
            float ps3 = __uint_as_float(s3u) + asi.w + asj.w;

            float m0 = msg_fast(pf0, ps0);
            float m1 = msg_fast(pf1, ps1);
            float m2 = msg_fast(pf2, ps2);
            float m3 = msg_fast(pf3, ps3);

            float* aout = &agg[(long long)d * HID + lane * 4];
            RED_ADD_V4F32(aout, m0, m1, m2, m3);
        }
    }
}

// ---------------- launch --------------------------------------------------------
static inline void gemm_launch(int act, const float* A, const float* B,
                               const float* bias, float* C, float* C2,
                               int M, int N, int K)
{
    dim3 grid((N + GBN - 1) / GBN, (M + GBM - 1) / GBM);
    if (act == 1) gemm_tf32_kernel<1><<<grid, 256, GEMM_SMEM>>>(A, B, bias, C, C2, M, N, K);
    else          gemm_tf32_kernel<0><<<grid, 256, GEMM_SMEM>>>(A, B, bias, C, C2, M, N, K);
}

extern "C" void kernel_launch(void* const* d_in, const int* in_sizes, int n_in,
                              void* d_out, int out_size)
{
    const float* x         = (const float*)d_in[0];
    const float* edge_attr = (const float*)d_in[1];
    const float* W_in      = (const float*)d_in[2];
    const float* b_in      = (const float*)d_in[3];
    const float* Wf        = (const float*)d_in[4];
    const float* bf        = (const float*)d_in[5];
    const float* Ws        = (const float*)d_in[6];
    const float* bs        = (const float*)d_in[7];
    const float* Wm        = (const float*)d_in[8];
    const float* bm        = (const float*)d_in[9];
    const int*   ei        = (const int*)d_in[10];   // int32
    float* out = (float*)d_out;

    const int* src = ei;
    const int* dst = ei + N_EDGES;

    float* h;     cudaGetSymbolAddress((void**)&h,     g_h);
    float* Apack; cudaGetSymbolAddress((void**)&Apack, g_Apack);
    float* agg;   cudaGetSymbolAddress((void**)&agg,   g_agg);
    float* Wpack; cudaGetSymbolAddress((void**)&Wpack, g_Wpack);

    static bool smem_set = false;
    if (!smem_set) {
        cudaFuncSetAttribute(edge_fused_kernel,
                             cudaFuncAttributeMaxDynamicSharedMemorySize, EDGE_SMEM);
        cudaFuncSetAttribute(gemm_tf32_kernel<0>,
                             cudaFuncAttributeMaxDynamicSharedMemorySize, GEMM_SMEM);
        cudaFuncSetAttribute(gemm_tf32_kernel<1>,
                             cudaFuncAttributeMaxDynamicSharedMemorySize, GEMM_SMEM);
        smem_set = true;
    }

    pack_weights_kernel<<<(2 * 128 * 512 + 255) / 256, 256>>>(Wf, Ws, Wpack);

    // h = relu(x @ W_in + b_in); dual-store into agg for layer 0
    gemm_launch(1, x, W_in, b_in, h, agg, N_NODES, HID, F_NODE);

    for (int l = 0; l < 2; l++) {
        const float* Wfl = Wf + (long long)l * 306 * HID;
        const float* Wsl = Ws + (long long)l * 306 * HID;
        const float* bfl = bf + l * HID;
        const float* bsl = bs + l * HID;
        const float* Wml = Wm + (long long)l * HID * HID;
        const float* bml = bm + l * HID;
        const float* Wpl = Wpack + (long long)l * 128 * 512;

        // all 4 node projections in one GEMM: Apack = h @ Wpack_l  [50000 x 512]
        gemm_launch(0, h, Wpl, nullptr, Apack, nullptr, N_NODES, 4 * HID, HID);

        // fused: edge projection (FFMA2, dup-ea) + fast message + v4 red
        edge_fused_kernel<<<N_EDGES / TE, 256, EDGE_SMEM>>>(
            edge_attr, Wfl + 256 * HID, Wsl + 256 * HID, bfl, bsl,
            Apack, src, dst, agg);

        // h = relu(agg @ Wm + bm); layer 0 dual-stores next agg; layer 1 -> out
        if (l == 0) gemm_launch(1, agg, Wml, bml, h, agg, N_NODES, HID, HID);
        else        gemm_launch(1, agg, Wml, bml, out, nullptr, N_NODES, HID, HID);
    }
}

// round 13
// speedup vs baseline: 1.0071x; 1.0071x over previous
#include <cuda_runtime.h>
#include <math.h>

#define N_NODES 50000
#define N_EDGES 800000
#define F_NODE  92
#define F_EDGE  50
#define HID     128

// ---------------- scratch (static device globals) ---------------------------
__device__ float g_h[N_NODES * HID];
__device__ float g_Apack[N_NODES * 4 * HID];    // [node][512]: Afi|Afj|Asi|Asj
__device__ float g_agg[N_NODES * HID];
__device__ float g_Wpack[2 * HID * 4 * HID];    // packed proj weights [l][128][512]

// ---------------- tf32 helpers ----------------------------------------------
__device__ __forceinline__ unsigned f2tf32(float f) {
    unsigned u;
    asm("cvt.rna.tf32.f32 %0, %1;" : "=r"(u) : "f"(f));
    return u;
}

__device__ __forceinline__ void mma_tf32(float& d0, float& d1, float& d2, float& d3,
                                         unsigned a0, unsigned a1, unsigned a2, unsigned a3,
                                         unsigned b0, unsigned b1)
{
    asm volatile(
        "mma.sync.aligned.m16n8k8.row.col.f32.tf32.tf32.f32 "
        "{%0,%1,%2,%3}, {%4,%5,%6,%7}, {%8,%9}, {%0,%1,%2,%3};"
        : "+f"(d0), "+f"(d1), "+f"(d2), "+f"(d3)
        : "r"(a0), "r"(a1), "r"(a2), "r"(a3), "r"(b0), "r"(b1));
}

// ---------------- packed f32x2 helpers (Blackwell FFMA2) ----------------------
#define FMA_F32X2(d, a, b, c) \
    asm("fma.rn.f32x2 %0, %1, %2, %3;" : "=l"(d) : "l"(a), "l"(b), "l"(c))
#define PACK_F32X2(out, lo, hi) \
    asm("mov.b64 %0, {%1, %2};" : "=l"(out) : "r"(lo), "r"(hi))
#define UNPACK_F32X2(lo, hi, in) \
    asm("mov.b64 {%0, %1}, %2;" : "=r"(lo), "=r"(hi) : "l"(in))

// vectorized global reduction
#define RED_ADD_V4F32(ptr, v0, v1, v2, v3) \
    asm volatile("red.global.add.v4.f32 [%0], {%1, %2, %3, %4};" \
                 :: "l"(ptr), "f"(v0), "f"(v1), "f"(v2), "f"(v3) : "memory")

// cp.async 16B with zero-fill predicate (src_bytes = 16 or 0)
__device__ __forceinline__ void cp_async16(void* smem_ptr, const void* gmem_ptr, int src_bytes) {
    unsigned saddr = (unsigned)__cvta_generic_to_shared(smem_ptr);
    asm volatile("cp.async.ca.shared.global [%0], [%1], 16, %2;"
                 :: "r"(saddr), "l"(gmem_ptr), "r"(src_bytes));
}
#define CP_ASYNC_COMMIT() asm volatile("cp.async.commit_group;")
#define CP_ASYNC_WAIT1()  asm volatile("cp.async.wait_group 1;")
#define CP_ASYNC_WAIT0()  asm volatile("cp.async.wait_group 0;")

// fast message math: sigmoid(pf) * softplus(ps), MUFU-based
__device__ __forceinline__ float msg_fast(float pf, float ps) {
    float sig = __fdividef(1.f, 1.f + __expf(-pf));
    float sp  = fmaxf(ps, 0.f) + __logf(1.f + __expf(-fabsf(ps)));
    return sig * sp;
}

// ---------------- tf32 GEMM, 2-stage cp.async pipeline, dual-store ------------
#define GBM 128
#define GBN 128
#define GBK 32
#define ASTR 36
#define BSTR 136
#define GEMM_SMEM ((2 * GBM * ASTR + 2 * GBK * BSTR) * 4)   // 71680 B

template<int ACT>  // 0 = none, 1 = relu
__global__ __launch_bounds__(256)
void gemm_tf32_kernel(const float* __restrict__ A, const float* __restrict__ B,
                      const float* __restrict__ bias, float* __restrict__ C,
                      float* __restrict__ C2,
                      int M, int N, int K)
{
    extern __shared__ float smem[];
    float* Asm = smem;                       // [2][GBM][ASTR]
    float* Bsm = smem + 2 * GBM * ASTR;      // [2][GBK][BSTR]

    const int tid  = threadIdx.x;
    const int lane = tid & 31;
    const int warp = tid >> 5;
    const int g    = lane >> 2;
    const int t    = lane & 3;

    const int row0 = blockIdx.y * GBM;
    const int col0 = blockIdx.x * GBN;
    const int wr0  = (warp >> 1) * 32;
    const int wc0  = (warp & 1) * 64;

    const int KT = (K + GBK - 1) / GBK;

    auto issue_tile = [&](int stage, int k0) {
        float* as = Asm + stage * GBM * ASTR;
        float* bs = Bsm + stage * GBK * BSTR;
#pragma unroll
        for (int i = 0; i < 4; i++) {
            int id = tid + i * 256;
            int r  = id >> 3;
            int cc = id & 7;
            int gr = row0 + r;
            int gc = k0 + cc * 4;
            int bytes = (gr < M && gc < K) ? 16 : 0;
            const float* src = bytes ? (A + (long long)gr * K + gc) : A;
            cp_async16(as + r * ASTR + cc * 4, src, bytes);
        }
#pragma unroll
        for (int i = 0; i < 4; i++) {
            int id = tid + i * 256;
            int r  = id >> 5;
            int cc = id & 31;
            int gr = k0 + r;
            int gc = col0 + cc * 4;
            int bytes = (gr < K && gc < N) ? 16 : 0;
            const float* src = bytes ? (B + (long long)gr * N + gc) : B;
            cp_async16(bs + r * BSTR + cc * 4, src, bytes);
        }
        CP_ASYNC_COMMIT();
    };

    float acc[2][8][4];
#pragma unroll
    for (int m = 0; m < 2; m++)
#pragma unroll
        for (int n = 0; n < 8; n++)
#pragma unroll
            for (int i = 0; i < 4; i++) acc[m][n][i] = 0.f;

    issue_tile(0, 0);

    for (int it = 0; it < KT; it++) {
        const int cur = it & 1;
        if (it + 1 < KT) {
            issue_tile((it + 1) & 1, (it + 1) * GBK);
            CP_ASYNC_WAIT1();
        } else {
            CP_ASYNC_WAIT0();
        }
        __syncthreads();

        const float* as = Asm + cur * GBM * ASTR;
        const float* bs = Bsm + cur * GBK * BSTR;

#pragma unroll
        for (int kk = 0; kk < GBK / 8; kk++) {
            const int kb = kk * 8;
            unsigned a[2][4];
#pragma unroll
            for (int m = 0; m < 2; m++) {
                int r = wr0 + m * 16;
                a[m][0] = f2tf32(as[(r + g    ) * ASTR + kb + t    ]);
                a[m][1] = f2tf32(as[(r + g + 8) * ASTR + kb + t    ]);
                a[m][2] = f2tf32(as[(r + g    ) * ASTR + kb + t + 4]);
                a[m][3] = f2tf32(as[(r + g + 8) * ASTR + kb + t + 4]);
            }
#pragma unroll
            for (int n = 0; n < 8; n++) {
                int c = wc0 + n * 8 + g;
                unsigned b0 = f2tf32(bs[(kb + t    ) * BSTR + c]);
                unsigned b1 = f2tf32(bs[(kb + t + 4) * BSTR + c]);
#pragma unroll
                for (int m = 0; m < 2; m++)
                    mma_tf32(acc[m][n][0], acc[m][n][1], acc[m][n][2], acc[m][n][3],
                             a[m][0], a[m][1], a[m][2], a[m][3], b0, b1);
            }
        }
        __syncthreads();
    }

#pragma unroll
    for (int m = 0; m < 2; m++) {
#pragma unroll
        for (int n = 0; n < 8; n++) {
            int gc = col0 + wc0 + n * 8 + 2 * t;
            float bx = 0.f, by = 0.f;
            if (bias) { bx = bias[gc]; by = bias[gc + 1]; }

            int gr0 = row0 + wr0 + m * 16 + g;
            if (gr0 < M) {
                float v0 = acc[m][n][0] + bx;
                float v1 = acc[m][n][1] + by;
                if (ACT == 1) { v0 = fmaxf(v0, 0.f); v1 = fmaxf(v1, 0.f); }
                float2 v = make_float2(v0, v1);
                *reinterpret_cast<float2*>(&C[(long long)gr0 * N + gc]) = v;
                if (C2) *reinterpret_cast<float2*>(&C2[(long long)gr0 * N + gc]) = v;
            }
            int gr1 = gr0 + 8;
            if (gr1 < M) {
                float v0 = acc[m][n][2] + bx;
                float v1 = acc[m][n][3] + by;
                if (ACT == 1) { v0 = fmaxf(v0, 0.f); v1 = fmaxf(v1, 0.f); }
                float2 v = make_float2(v0, v1);
                *reinterpret_cast<float2*>(&C[(long long)gr1 * N + gc]) = v;
                if (C2) *reinterpret_cast<float2*>(&C2[(long long)gr1 * N + gc]) = v;
            }
        }
    }
}

// ---------------- weight pack -------------------------------------------------
__global__ void pack_weights_kernel(const float* __restrict__ Wf,
                                    const float* __restrict__ Ws,
                                    float* __restrict__ Wpack)
{
    int idx = blockIdx.x * 256 + threadIdx.x;
    if (idx >= 2 * 128 * 512) return;
    int l = idx >> 16;
    int k = (idx >> 9) & 127;
    int c = idx & 511;
    int sel = c >> 7;
    int j = c & 127;
    const float* W = (sel < 2) ? Wf : Ws;
    int row = (sel & 1) ? (128 + k) : k;
    Wpack[idx] = W[(long long)l * 306 * 128 + row * 128 + j];
}

// ---------------- fused edge kernel (8-edge ILP, FFMA2, LDS.128 dup-ea) -------
#define TE 128
// smem: Wf 6400 f + Ws 6400 f + ea2 (TE*50 float2) = 102400 B
#define EDGE_SMEM (6400 * 4 + 6400 * 4 + TE * F_EDGE * 8)

__global__ __launch_bounds__(256, 2)
void edge_fused_kernel(const float* __restrict__ edge_attr,
                       const float* __restrict__ Wfe,   // [50][128]
                       const float* __restrict__ Wse,   // [50][128]
                       const float* __restrict__ bf_l,
                       const float* __restrict__ bs_l,
                       const float* __restrict__ Apack, // [N_NODES][512]
                       const int* __restrict__ src_idx,
                       const int* __restrict__ dst_idx,
                       float* __restrict__ agg)
{
    extern __shared__ float sm[];
    float* Wf_s = sm;                  // 6400 floats
    float* Ws_s = sm + 6400;           // 6400 floats
    float2* ea2 = reinterpret_cast<float2*>(sm + 12800);   // [TE*50] duplicated {v,v}

    const int tid  = threadIdx.x;
    const int lane = tid & 31;
    const int warp = tid >> 5;
    const int e0   = blockIdx.x * TE;

    // load weights (float4, coalesced)
    {
        const float4* wf4 = reinterpret_cast<const float4*>(Wfe);
        const float4* ws4 = reinterpret_cast<const float4*>(Wse);
        float4* sf4 = reinterpret_cast<float4*>(Wf_s);
        float4* ss4 = reinterpret_cast<float4*>(Ws_s);
#pragma unroll
        for (int i = 0; i < 7; i++) {
            int idx = tid + i * 256;
            if (idx < 1600) { sf4[idx] = wf4[idx]; ss4[idx] = ws4[idx]; }
        }
    }
    // load edge_attr tile, duplicated into f32x2 pairs
    {
        const float* gbase = edge_attr + (long long)e0 * F_EDGE;
#pragma unroll
        for (int i = 0; i < (TE * F_EDGE) / 256; i++) {
            int idx = tid + i * 256;
            float v = gbase[idx];
            ea2[idx] = make_float2(v, v);
        }
    }
    __syncthreads();

    const float4 bf4 = *reinterpret_cast<const float4*>(bf_l + lane * 4);
    const float4 bs4 = *reinterpret_cast<const float4*>(bs_l + lane * 4);
    unsigned long long bf01, bf23, bs01, bs23;
    PACK_F32X2(bf01, __float_as_uint(bf4.x), __float_as_uint(bf4.y));
    PACK_F32X2(bf23, __float_as_uint(bf4.z), __float_as_uint(bf4.w));
    PACK_F32X2(bs01, __float_as_uint(bs4.x), __float_as_uint(bs4.y));
    PACK_F32X2(bs23, __float_as_uint(bs4.z), __float_as_uint(bs4.w));

    // each warp handles 16 edges, 8 at a time
#pragma unroll 1
    for (int grp = 0; grp < 2; grp++) {
        const int elb = warp * 16 + grp * 8;

        unsigned long long af01[8], af23[8], as01[8], as23[8];
#pragma unroll
        for (int q = 0; q < 8; q++) {
            af01[q] = bf01; af23[q] = bf23;
            as01[q] = bs01; as23[q] = bs23;
        }

#pragma unroll 1
        for (int k = 0; k < F_EDGE; k += 2) {
            const ulonglong2 wf0 = *reinterpret_cast<const ulonglong2*>(&Wf_s[k * 128 + lane * 4]);
            const ulonglong2 ws0 = *reinterpret_cast<const ulonglong2*>(&Ws_s[k * 128 + lane * 4]);
            const ulonglong2 wf1 = *reinterpret_cast<const ulonglong2*>(&Wf_s[(k + 1) * 128 + lane * 4]);
            const ulonglong2 ws1 = *reinterpret_cast<const ulonglong2*>(&Ws_s[(k + 1) * 128 + lane * 4]);

#pragma unroll
            for (int q = 0; q < 8; q++) {
                // ONE LDS.128 broadcast: {ea[k],ea[k],ea[k+1],ea[k+1]} — 1 wavefront, 0 movs
                const ulonglong2 av =
                    *reinterpret_cast<const ulonglong2*>(&ea2[(elb + q) * F_EDGE + k]);
                const unsigned long long alo = av.x;
                const unsigned long long ahi = av.y;

                FMA_F32X2(af01[q], alo, wf0.x, af01[q]);
                FMA_F32X2(af23[q], alo, wf0.y, af23[q]);
                FMA_F32X2(as01[q], alo, ws0.x, as01[q]);
                FMA_F32X2(as23[q], alo, ws0.y, as23[q]);
                FMA_F32X2(af01[q], ahi, wf1.x, af01[q]);
                FMA_F32X2(af23[q], ahi, wf1.y, af23[q]);
                FMA_F32X2(as01[q], ahi, ws1.x, as01[q]);
                FMA_F32X2(as23[q], ahi, ws1.y, as23[q]);
            }
        }

#pragma unroll
        for (int q = 0; q < 8; q++) {
            const int e = e0 + elb + q;
            const int s = src_idx[e];
            const int d = dst_idx[e];

            unsigned f0u, f1u, f2u, f3u, s0u, s1u, s2u, s3u;
            UNPACK_F32X2(f0u, f1u, af01[q]);
            UNPACK_F32X2(f2u, f3u, af23[q]);
            UNPACK_F32X2(s0u, s1u, as01[q]);
            UNPACK_F32X2(s2u, s3u, as23[q]);

            const float4 afi = *reinterpret_cast<const float4*>(&Apack[(long long)d * 512 + lane * 4]);
            const float4 afj = *reinterpret_cast<const float4*>(&Apack[(long long)s * 512 + 128 + lane * 4]);
            const float4 asi = *reinterpret_cast<const float4*>(&Apack[(long long)d * 512 + 256 + lane * 4]);
            const float4 asj = *reinterpret_cast<const float4*>(&Apack[(long long)s * 512 + 384 + lane * 4]);

            float pf0 = __uint_as_float(f0u) + afi.x + afj.x;
            float pf1 = __uint_as_float(f1u) + afi.y + afj.y;
            float pf2 = __uint_as_float(f2u) + afi.z + afj.z;
            float pf3 = __uint_as_float(f3u) + afi.w + afj.w;
            float ps0 = __uint_as_float(s0u) + asi.x + asj.x;
            float ps1 = __uint_as_float(s1u) + asi.y + asj.y;
            float ps2 = __uint_as_float(s2u) + asi.z + asj.z;
            float ps3 = __uint_as_float(s3u) + asi.w + asj.w;

            float m0 = msg_fast(pf0, ps0);
            float m1 = msg_fast(pf1, ps1);
            float m2 = msg_fast(pf2, ps2);
            float m3 = msg_fast(pf3, ps3);

            float* aout = &agg[(long long)d * HID + lane * 4];
            RED_ADD_V4F32(aout, m0, m1, m2, m3);
        }
    }
}

// ---------------- launch --------------------------------------------------------
static inline void gemm_launch(int act, const float* A, const float* B,
                               const float* bias, float* C, float* C2,
                               int M, int N, int K)
{
    dim3 grid((N + GBN - 1) / GBN, (M + GBM - 1) / GBM);
    if (act == 1) gemm_tf32_kernel<1><<<grid, 256, GEMM_SMEM>>>(A, B, bias, C, C2, M, N, K);
    else          gemm_tf32_kernel<0><<<grid, 256, GEMM_SMEM>>>(A, B, bias, C, C2, M, N, K);
}

extern "C" void kernel_launch(void* const* d_in, const int* in_sizes, int n_in,
                              void* d_out, int out_size)
{
    const float* x         = (const float*)d_in[0];
    const float* edge_attr = (const float*)d_in[1];
    const float* W_in      = (const float*)d_in[2];
    const float* b_in      = (const float*)d_in[3];
    const float* Wf        = (const float*)d_in[4];
    const float* bf        = (const float*)d_in[5];
    const float* Ws        = (const float*)d_in[6];
    const float* bs        = (const float*)d_in[7];
    const float* Wm        = (const float*)d_in[8];
    const float* bm        = (const float*)d_in[9];
    const int*   ei        = (const int*)d_in[10];   // int32
    float* out = (float*)d_out;

    const int* src = ei;
    const int* dst = ei + N_EDGES;

    float* h;     cudaGetSymbolAddress((void**)&h,     g_h);
    float* Apack; cudaGetSymbolAddress((void**)&Apack, g_Apack);
    float* agg;   cudaGetSymbolAddress((void**)&agg,   g_agg);
    float* Wpack; cudaGetSymbolAddress((void**)&Wpack, g_Wpack);

    static bool smem_set = false;
    if (!smem_set) {
        cudaFuncSetAttribute(edge_fused_kernel,
                             cudaFuncAttributeMaxDynamicSharedMemorySize, EDGE_SMEM);
        cudaFuncSetAttribute(gemm_tf32_kernel<0>,
                             cudaFuncAttributeMaxDynamicSharedMemorySize, GEMM_SMEM);
        cudaFuncSetAttribute(gemm_tf32_kernel<1>,
                             cudaFuncAttributeMaxDynamicSharedMemorySize, GEMM_SMEM);
        smem_set = true;
    }

    pack_weights_kernel<<<(2 * 128 * 512 + 255) / 256, 256>>>(Wf, Ws, Wpack);

    // h = relu(x @ W_in + b_in); dual-store into agg for layer 0
    gemm_launch(1, x, W_in, b_in, h, agg, N_NODES, HID, F_NODE);

    for (int l = 0; l < 2; l++) {
        const float* Wfl = Wf + (long long)l * 306 * HID;
        const float* Wsl = Ws + (long long)l * 306 * HID;
        const float* bfl = bf + l * HID;
        const float* bsl = bs + l * HID;
        const float* Wml = Wm + (long long)l * HID * HID;
        const float* bml = bm + l * HID;
        const float* Wpl = Wpack + (long long)l * 128 * 512;

        // all 4 node projections in one GEMM: Apack = h @ Wpack_l  [50000 x 512]
        gemm_launch(0, h, Wpl, nullptr, Apack, nullptr, N_NODES, 4 * HID, HID);

        // fused: edge projection (FFMA2, LDS.128 dup-ea) + fast message + v4 red
        edge_fused_kernel<<<N_EDGES / TE, 256, EDGE_SMEM>>>(
            edge_attr, Wfl + 256 * HID, Wsl + 256 * HID, bfl, bsl,
            Apack, src, dst, agg);

        // h = relu(agg @ Wm + bm); layer 0 dual-stores next agg; layer 1 -> out
        if (l == 0) gemm_launch(1, agg, Wml, bml, h, agg, N_NODES, HID, HID);
        else        gemm_launch(1, agg, Wml, bml, out, nullptr, N_NODES, HID, HID);
    }
}

// round 14
// speedup vs baseline: 1.1551x; 1.1469x over previous
#include <cuda_runtime.h>
#include <math.h>

#define N_NODES 50000
#define N_EDGES 800000
#define F_NODE  92
#define F_EDGE  50
#define HID     128

// ---------------- scratch (static device globals) ---------------------------
__device__ float g_h[N_NODES * HID];
__device__ float g_Apack[N_NODES * 4 * HID];    // [node][512]: Afi|Afj|Asi|Asj
__device__ float g_agg[N_NODES * HID];
__device__ float g_Wpack[2 * HID * 4 * HID];    // packed proj weights [l][128][512]

// ---------------- tf32 helpers ----------------------------------------------
__device__ __forceinline__ unsigned f2tf32(float f) {
    unsigned u;
    asm("cvt.rna.tf32.f32 %0, %1;" : "=r"(u) : "f"(f));
    return u;
}

__device__ __forceinline__ void mma_tf32(float& d0, float& d1, float& d2, float& d3,
                                         unsigned a0, unsigned a1, unsigned a2, unsigned a3,
                                         unsigned b0, unsigned b1)
{
    asm volatile(
        "mma.sync.aligned.m16n8k8.row.col.f32.tf32.tf32.f32 "
        "{%0,%1,%2,%3}, {%4,%5,%6,%7}, {%8,%9}, {%0,%1,%2,%3};"
        : "+f"(d0), "+f"(d1), "+f"(d2), "+f"(d3)
        : "r"(a0), "r"(a1), "r"(a2), "r"(a3), "r"(b0), "r"(b1));
}

// ---------------- packed f32x2 helpers (Blackwell FFMA2) ----------------------
#define FMA_F32X2(d, a, b, c) \
    asm("fma.rn.f32x2 %0, %1, %2, %3;" : "=l"(d) : "l"(a), "l"(b), "l"(c))
#define PACK_F32X2(out, lo, hi) \
    asm("mov.b64 %0, {%1, %2};" : "=l"(out) : "r"(lo), "r"(hi))
#define UNPACK_F32X2(lo, hi, in) \
    asm("mov.b64 {%0, %1}, %2;" : "=r"(lo), "=r"(hi) : "l"(in))

// vectorized global reduction
#define RED_ADD_V4F32(ptr, v0, v1, v2, v3) \
    asm volatile("red.global.add.v4.f32 [%0], {%1, %2, %3, %4};" \
                 :: "l"(ptr), "f"(v0), "f"(v1), "f"(v2), "f"(v3) : "memory")

// cp.async 16B with zero-fill predicate (src_bytes = 16 or 0)
__device__ __forceinline__ void cp_async16(void* smem_ptr, const void* gmem_ptr, int src_bytes) {
    unsigned saddr = (unsigned)__cvta_generic_to_shared(smem_ptr);
    asm volatile("cp.async.ca.shared.global [%0], [%1], 16, %2;"
                 :: "r"(saddr), "l"(gmem_ptr), "r"(src_bytes));
}
#define CP_ASYNC_COMMIT() asm volatile("cp.async.commit_group;")
#define CP_ASYNC_WAIT1()  asm volatile("cp.async.wait_group 1;")
#define CP_ASYNC_WAIT0()  asm volatile("cp.async.wait_group 0;")

// fast message math: sigmoid(pf) * softplus(ps), MUFU-based
__device__ __forceinline__ float msg_fast(float pf, float ps) {
    float sig = __fdividef(1.f, 1.f + __expf(-pf));
    float sp  = fmaxf(ps, 0.f) + __logf(1.f + __expf(-fabsf(ps)));
    return sig * sp;
}

// ---------------- tf32 GEMM, 2-stage cp.async pipeline, dual-store ------------
#define GBM 128
#define GBN 128
#define GBK 32
#define ASTR 36
#define BSTR 136
#define GEMM_SMEM ((2 * GBM * ASTR + 2 * GBK * BSTR) * 4)   // 71680 B

template<int ACT>  // 0 = none, 1 = relu
__global__ __launch_bounds__(256)
void gemm_tf32_kernel(const float* __restrict__ A, const float* __restrict__ B,
                      const float* __restrict__ bias, float* __restrict__ C,
                      float* __restrict__ C2,
                      int M, int N, int K)
{
    extern __shared__ float smem[];
    float* Asm = smem;                       // [2][GBM][ASTR]
    float* Bsm = smem + 2 * GBM * ASTR;      // [2][GBK][BSTR]

    const int tid  = threadIdx.x;
    const int lane = tid & 31;
    const int warp = tid >> 5;
    const int g    = lane >> 2;
    const int t    = lane & 3;

    const int row0 = blockIdx.y * GBM;
    const int col0 = blockIdx.x * GBN;
    const int wr0  = (warp >> 1) * 32;
    const int wc0  = (warp & 1) * 64;

    const int KT = (K + GBK - 1) / GBK;

    auto issue_tile = [&](int stage, int k0) {
        float* as = Asm + stage * GBM * ASTR;
        float* bs = Bsm + stage * GBK * BSTR;
#pragma unroll
        for (int i = 0; i < 4; i++) {
            int id = tid + i * 256;
            int r  = id >> 3;
            int cc = id & 7;
            int gr = row0 + r;
            int gc = k0 + cc * 4;
            int bytes = (gr < M && gc < K) ? 16 : 0;
            const float* src = bytes ? (A + (long long)gr * K + gc) : A;
            cp_async16(as + r * ASTR + cc * 4, src, bytes);
        }
#pragma unroll
        for (int i = 0; i < 4; i++) {
            int id = tid + i * 256;
            int r  = id >> 5;
            int cc = id & 31;
            int gr = k0 + r;
            int gc = col0 + cc * 4;
            int bytes = (gr < K && gc < N) ? 16 : 0;
            const float* src = bytes ? (B + (long long)gr * N + gc) : B;
            cp_async16(bs + r * BSTR + cc * 4, src, bytes);
        }
        CP_ASYNC_COMMIT();
    };

    float acc[2][8][4];
#pragma unroll
    for (int m = 0; m < 2; m++)
#pragma unroll
        for (int n = 0; n < 8; n++)
#pragma unroll
            for (int i = 0; i < 4; i++) acc[m][n][i] = 0.f;

    issue_tile(0, 0);

    for (int it = 0; it < KT; it++) {
        const int cur = it & 1;
        if (it + 1 < KT) {
            issue_tile((it + 1) & 1, (it + 1) * GBK);
            CP_ASYNC_WAIT1();
        } else {
            CP_ASYNC_WAIT0();
        }
        __syncthreads();

        const float* as = Asm + cur * GBM * ASTR;
        const float* bs = Bsm + cur * GBK * BSTR;

#pragma unroll
        for (int kk = 0; kk < GBK / 8; kk++) {
            const int kb = kk * 8;
            unsigned a[2][4];
#pragma unroll
            for (int m = 0; m < 2; m++) {
                int r = wr0 + m * 16;
                a[m][0] = f2tf32(as[(r + g    ) * ASTR + kb + t    ]);
                a[m][1] = f2tf32(as[(r + g + 8) * ASTR + kb + t    ]);
                a[m][2] = f2tf32(as[(r + g    ) * ASTR + kb + t + 4]);
                a[m][3] = f2tf32(as[(r + g + 8) * ASTR + kb + t + 4]);
            }
#pragma unroll
            for (int n = 0; n < 8; n++) {
                int c = wc0 + n * 8 + g;
                unsigned b0 = f2tf32(bs[(kb + t    ) * BSTR + c]);
                unsigned b1 = f2tf32(bs[(kb + t + 4) * BSTR + c]);
#pragma unroll
                for (int m = 0; m < 2; m++)
                    mma_tf32(acc[m][n][0], acc[m][n][1], acc[m][n][2], acc[m][n][3],
                             a[m][0], a[m][1], a[m][2], a[m][3], b0, b1);
            }
        }
        __syncthreads();
    }

#pragma unroll
    for (int m = 0; m < 2; m++) {
#pragma unroll
        for (int n = 0; n < 8; n++) {
            int gc = col0 + wc0 + n * 8 + 2 * t;
            float bx = 0.f, by = 0.f;
            if (bias) { bx = bias[gc]; by = bias[gc + 1]; }

            int gr0 = row0 + wr0 + m * 16 + g;
            if (gr0 < M) {
                float v0 = acc[m][n][0] + bx;
                float v1 = acc[m][n][1] + by;
                if (ACT == 1) { v0 = fmaxf(v0, 0.f); v1 = fmaxf(v1, 0.f); }
                float2 v = make_float2(v0, v1);
                *reinterpret_cast<float2*>(&C[(long long)gr0 * N + gc]) = v;
                if (C2) *reinterpret_cast<float2*>(&C2[(long long)gr0 * N + gc]) = v;
            }
            int gr1 = gr0 + 8;
            if (gr1 < M) {
                float v0 = acc[m][n][2] + bx;
                float v1 = acc[m][n][3] + by;
                if (ACT == 1) { v0 = fmaxf(v0, 0.f); v1 = fmaxf(v1, 0.f); }
                float2 v = make_float2(v0, v1);
                *reinterpret_cast<float2*>(&C[(long long)gr1 * N + gc]) = v;
                if (C2) *reinterpret_cast<float2*>(&C2[(long long)gr1 * N + gc]) = v;
            }
        }
    }
}

// ---------------- weight pack -------------------------------------------------
__global__ void pack_weights_kernel(const float* __restrict__ Wf,
                                    const float* __restrict__ Ws,
                                    float* __restrict__ Wpack)
{
    int idx = blockIdx.x * 256 + threadIdx.x;
    if (idx >= 2 * 128 * 512) return;
    int l = idx >> 16;
    int k = (idx >> 9) & 127;
    int c = idx & 511;
    int sel = c >> 7;
    int j = c & 127;
    const float* W = (sel < 2) ? Wf : Ws;
    int row = (sel & 1) ? (128 + k) : k;
    Wpack[idx] = W[(long long)l * 306 * 128 + row * 128 + j];
}

// ---------------- fused edge kernel (8-edge ILP, FFMA2, fast act, v4 red) -----
// Exact bench-R11 configuration: scalar float2 ea loads + PACK movs, 76.8KB smem.
#define TE 128
#define EDGE_SMEM ((6400 + 6400 + TE * F_EDGE) * 4)   // 76800 B

__global__ __launch_bounds__(256, 2)
void edge_fused_kernel(const float* __restrict__ edge_attr,
                       const float* __restrict__ Wfe,   // [50][128]
                       const float* __restrict__ Wse,   // [50][128]
                       const float* __restrict__ bf_l,
                       const float* __restrict__ bs_l,
                       const float* __restrict__ Apack, // [N_NODES][512]
                       const int* __restrict__ src_idx,
                       const int* __restrict__ dst_idx,
                       float* __restrict__ agg)
{
    extern __shared__ float sm[];
    float* Wf_s = sm;                 // 6400 floats
    float* Ws_s = sm + 6400;          // 6400 floats
    float* ea_s = sm + 12800;         // TE*50 floats

    const int tid  = threadIdx.x;
    const int lane = tid & 31;
    const int warp = tid >> 5;
    const int e0   = blockIdx.x * TE;

    // load weights (float4, coalesced)
    {
        const float4* wf4 = reinterpret_cast<const float4*>(Wfe);
        const float4* ws4 = reinterpret_cast<const float4*>(Wse);
        float4* sf4 = reinterpret_cast<float4*>(Wf_s);
        float4* ss4 = reinterpret_cast<float4*>(Ws_s);
#pragma unroll
        for (int i = 0; i < 7; i++) {
            int idx = tid + i * 256;
            if (idx < 1600) { sf4[idx] = wf4[idx]; ss4[idx] = ws4[idx]; }
        }
    }
    // load edge_attr tile
    {
        const float* gbase = edge_attr + (long long)e0 * F_EDGE;
#pragma unroll
        for (int i = 0; i < (TE * F_EDGE) / 256; i++) {
            int idx = tid + i * 256;
            ea_s[idx] = gbase[idx];
        }
    }
    __syncthreads();

    const float4 bf4 = *reinterpret_cast<const float4*>(bf_l + lane * 4);
    const float4 bs4 = *reinterpret_cast<const float4*>(bs_l + lane * 4);
    unsigned long long bf01, bf23, bs01, bs23;
    PACK_F32X2(bf01, __float_as_uint(bf4.x), __float_as_uint(bf4.y));
    PACK_F32X2(bf23, __float_as_uint(bf4.z), __float_as_uint(bf4.w));
    PACK_F32X2(bs01, __float_as_uint(bs4.x), __float_as_uint(bs4.y));
    PACK_F32X2(bs23, __float_as_uint(bs4.z), __float_as_uint(bs4.w));

    // each warp handles 16 edges, 8 at a time (W LDS amortized over 8 edges)
#pragma unroll 1
    for (int grp = 0; grp < 2; grp++) {
        const int elb = warp * 16 + grp * 8;

        unsigned long long af01[8], af23[8], as01[8], as23[8];
#pragma unroll
        for (int q = 0; q < 8; q++) {
            af01[q] = bf01; af23[q] = bf23;
            as01[q] = bs01; as23[q] = bs23;
        }

        // k loop: 2 k's at a time; ea via broadcast float2
#pragma unroll 1
        for (int k = 0; k < F_EDGE; k += 2) {
            const ulonglong2 wf0 = *reinterpret_cast<const ulonglong2*>(&Wf_s[k * 128 + lane * 4]);
            const ulonglong2 ws0 = *reinterpret_cast<const ulonglong2*>(&Ws_s[k * 128 + lane * 4]);
            const ulonglong2 wf1 = *reinterpret_cast<const ulonglong2*>(&Wf_s[(k + 1) * 128 + lane * 4]);
            const ulonglong2 ws1 = *reinterpret_cast<const ulonglong2*>(&Ws_s[(k + 1) * 128 + lane * 4]);

#pragma unroll
            for (int q = 0; q < 8; q++) {
                const float2 av = *reinterpret_cast<const float2*>(&ea_s[(elb + q) * F_EDGE + k]);
                unsigned long long alo, ahi;
                unsigned ulo = __float_as_uint(av.x);
                unsigned uhi = __float_as_uint(av.y);
                PACK_F32X2(alo, ulo, ulo);
                PACK_F32X2(ahi, uhi, uhi);

                FMA_F32X2(af01[q], alo, wf0.x, af01[q]);
                FMA_F32X2(af23[q], alo, wf0.y, af23[q]);
                FMA_F32X2(as01[q], alo, ws0.x, as01[q]);
                FMA_F32X2(as23[q], alo, ws0.y, as23[q]);
                FMA_F32X2(af01[q], ahi, wf1.x, af01[q]);
                FMA_F32X2(af23[q], ahi, wf1.y, af23[q]);
                FMA_F32X2(as01[q], ahi, ws1.x, as01[q]);
                FMA_F32X2(as23[q], ahi, ws1.y, as23[q]);
            }
        }

#pragma unroll
        for (int q = 0; q < 8; q++) {
            const int e = e0 + elb + q;
            const int s = src_idx[e];
            const int d = dst_idx[e];

            unsigned f0u, f1u, f2u, f3u, s0u, s1u, s2u, s3u;
            UNPACK_F32X2(f0u, f1u, af01[q]);
            UNPACK_F32X2(f2u, f3u, af23[q]);
            UNPACK_F32X2(s0u, s1u, as01[q]);
            UNPACK_F32X2(s2u, s3u, as23[q]);

            const float4 afi = *reinterpret_cast<const float4*>(&Apack[(long long)d * 512 + lane * 4]);
            const float4 afj = *reinterpret_cast<const float4*>(&Apack[(long long)s * 512 + 128 + lane * 4]);
            const float4 asi = *reinterpret_cast<const float4*>(&Apack[(long long)d * 512 + 256 + lane * 4]);
            const float4 asj = *reinterpret_cast<const float4*>(&Apack[(long long)s * 512 + 384 + lane * 4]);

            float pf0 = __uint_as_float(f0u) + afi.x + afj.x;
            float pf1 = __uint_as_float(f1u) + afi.y + afj.y;
            float pf2 = __uint_as_float(f2u) + afi.z + afj.z;
            float pf3 = __uint_as_float(f3u) + afi.w + afj.w;
            float ps0 = __uint_as_float(s0u) + asi.x + asj.x;
            float ps1 = __uint_as_float(s1u) + asi.y + asj.y;
            float ps2 = __uint_as_float(s2u) + asi.z + asj.z;
            float ps3 = __uint_as_float(s3u) + asi.w + asj.w;

            float m0 = msg_fast(pf0, ps0);
            float m1 = msg_fast(pf1, ps1);
            float m2 = msg_fast(pf2, ps2);
            float m3 = msg_fast(pf3, ps3);

            float* aout = &agg[(long long)d * HID + lane * 4];
            RED_ADD_V4F32(aout, m0, m1, m2, m3);
        }
    }
}

// ---------------- launch --------------------------------------------------------
static inline void gemm_launch(int act, const float* A, const float* B,
                               const float* bias, float* C, float* C2,
                               int M, int N, int K)
{
    dim3 grid((N + GBN - 1) / GBN, (M + GBM - 1) / GBM);
    if (act == 1) gemm_tf32_kernel<1><<<grid, 256, GEMM_SMEM>>>(A, B, bias, C, C2, M, N, K);
    else          gemm_tf32_kernel<0><<<grid, 256, GEMM_SMEM>>>(A, B, bias, C, C2, M, N, K);
}

extern "C" void kernel_launch(void* const* d_in, const int* in_sizes, int n_in,
                              void* d_out, int out_size)
{
    const float* x         = (const float*)d_in[0];
    const float* edge_attr = (const float*)d_in[1];
    const float* W_in      = (const float*)d_in[2];
    const float* b_in      = (const float*)d_in[3];
    const float* Wf        = (const float*)d_in[4];
    const float* bf        = (const float*)d_in[5];
    const float* Ws        = (const float*)d_in[6];
    const float* bs        = (const float*)d_in[7];
    const float* Wm        = (const float*)d_in[8];
    const float* bm        = (const float*)d_in[9];
    const int*   ei        = (const int*)d_in[10];   // int32
    float* out = (float*)d_out;

    const int* src = ei;
    const int* dst = ei + N_EDGES;

    float* h;     cudaGetSymbolAddress((void**)&h,     g_h);
    float* Apack; cudaGetSymbolAddress((void**)&Apack, g_Apack);
    float* agg;   cudaGetSymbolAddress((void**)&agg,   g_agg);
    float* Wpack; cudaGetSymbolAddress((void**)&Wpack, g_Wpack);

    static bool smem_set = false;
    if (!smem_set) {
        cudaFuncSetAttribute(edge_fused_kernel,
                             cudaFuncAttributeMaxDynamicSharedMemorySize, EDGE_SMEM);
        cudaFuncSetAttribute(gemm_tf32_kernel<0>,
                             cudaFuncAttributeMaxDynamicSharedMemorySize, GEMM_SMEM);
        cudaFuncSetAttribute(gemm_tf32_kernel<1>,
                             cudaFuncAttributeMaxDynamicSharedMemorySize, GEMM_SMEM);
        smem_set = true;
    }

    pack_weights_kernel<<<(2 * 128 * 512 + 255) / 256, 256>>>(Wf, Ws, Wpack);

    // h = relu(x @ W_in + b_in); dual-store into agg for layer 0
    gemm_launch(1, x, W_in, b_in, h, agg, N_NODES, HID, F_NODE);

    for (int l = 0; l < 2; l++) {
        const float* Wfl = Wf + (long long)l * 306 * HID;
        const float* Wsl = Ws + (long long)l * 306 * HID;
        const float* bfl = bf + l * HID;
        const float* bsl = bs + l * HID;
        const float* Wml = Wm + (long long)l * HID * HID;
        const float* bml = bm + l * HID;
        const float* Wpl = Wpack + (long long)l * 128 * 512;

        // all 4 node projections in one GEMM: Apack = h @ Wpack_l  [50000 x 512]
        gemm_launch(0, h, Wpl, nullptr, Apack, nullptr, N_NODES, 4 * HID, HID);

        // fused: edge projection (FFMA2, 8-edge ILP) + fast message + v4 red
        edge_fused_kernel<<<N_EDGES / TE, 256, EDGE_SMEM>>>(
            edge_attr, Wfl + 256 * HID, Wsl + 256 * HID, bfl, bsl,
            Apack, src, dst, agg);

        // h = relu(agg @ Wm + bm); layer 0 dual-stores next agg; layer 1 -> out
        if (l == 0) gemm_launch(1, agg, Wml, bml, h, agg, N_NODES, HID, HID);
        else        gemm_launch(1, agg, Wml, bml, out, nullptr, N_NODES, HID, HID);
    }
}

// round 15
// speedup vs baseline: 1.1949x; 1.0345x over previous
#include <cuda_runtime.h>
#include <math.h>

#define N_NODES 50000
#define N_EDGES 800000
#define F_NODE  92
#define F_EDGE  50
#define HID     128

// ---------------- scratch (static device globals) ---------------------------
__device__ float g_h[N_NODES * HID];
__device__ float g_Apack[N_NODES * 4 * HID];    // [node][512]: Afi|Afj|Asi|Asj
__device__ float g_agg[N_NODES * HID];
__device__ float g_Wpack[2 * HID * 4 * HID];    // packed proj weights [l][128][512]

// ---------------- tf32 helpers ----------------------------------------------
__device__ __forceinline__ unsigned f2tf32(float f) {
    unsigned u;
    asm("cvt.rna.tf32.f32 %0, %1;" : "=r"(u) : "f"(f));
    return u;
}

__device__ __forceinline__ void mma_tf32(float& d0, float& d1, float& d2, float& d3,
                                         unsigned a0, unsigned a1, unsigned a2, unsigned a3,
                                         unsigned b0, unsigned b1)
{
    asm volatile(
        "mma.sync.aligned.m16n8k8.row.col.f32.tf32.tf32.f32 "
        "{%0,%1,%2,%3}, {%4,%5,%6,%7}, {%8,%9}, {%0,%1,%2,%3};"
        : "+f"(d0), "+f"(d1), "+f"(d2), "+f"(d3)
        : "r"(a0), "r"(a1), "r"(a2), "r"(a3), "r"(b0), "r"(b1));
}

// ---------------- packed f32x2 helpers (Blackwell FFMA2) ----------------------
#define FMA_F32X2(d, a, b, c) \
    asm("fma.rn.f32x2 %0, %1, %2, %3;" : "=l"(d) : "l"(a), "l"(b), "l"(c))
#define PACK_F32X2(out, lo, hi) \
    asm("mov.b64 %0, {%1, %2};" : "=l"(out) : "r"(lo), "r"(hi))
#define UNPACK_F32X2(lo, hi, in) \
    asm("mov.b64 {%0, %1}, %2;" : "=r"(lo), "=r"(hi) : "l"(in))

// vectorized global reduction
#define RED_ADD_V4F32(ptr, v0, v1, v2, v3) \
    asm volatile("red.global.add.v4.f32 [%0], {%1, %2, %3, %4};" \
                 :: "l"(ptr), "f"(v0), "f"(v1), "f"(v2), "f"(v3) : "memory")

// cp.async 16B with zero-fill predicate (src_bytes = 16 or 0)
__device__ __forceinline__ void cp_async16(void* smem_ptr, const void* gmem_ptr, int src_bytes) {
    unsigned saddr = (unsigned)__cvta_generic_to_shared(smem_ptr);
    asm volatile("cp.async.ca.shared.global [%0], [%1], 16, %2;"
                 :: "r"(saddr), "l"(gmem_ptr), "r"(src_bytes));
}
#define CP_ASYNC_COMMIT() asm volatile("cp.async.commit_group;")
#define CP_ASYNC_WAIT1()  asm volatile("cp.async.wait_group 1;")
#define CP_ASYNC_WAIT0()  asm volatile("cp.async.wait_group 0;")

// fast message math: sigmoid(pf) * softplus(ps), MUFU-based
__device__ __forceinline__ float msg_fast(float pf, float ps) {
    float sig = __fdividef(1.f, 1.f + __expf(-pf));
    float sp  = fmaxf(ps, 0.f) + __logf(1.f + __expf(-fabsf(ps)));
    return sig * sp;
}

// ---------------- tf32 GEMM, 2-stage cp.async pipeline, dual-store ------------
#define GBM 128
#define GBN 128
#define GBK 32
#define ASTR 36
#define BSTR 136
#define GEMM_SMEM ((2 * GBM * ASTR + 2 * GBK * BSTR) * 4)   // 71680 B

template<int ACT>  // 0 = none, 1 = relu
__global__ __launch_bounds__(256)
void gemm_tf32_kernel(const float* __restrict__ A, const float* __restrict__ B,
                      const float* __restrict__ bias, float* __restrict__ C,
                      float* __restrict__ C2,
                      int M, int N, int K)
{
    extern __shared__ float smem[];
    float* Asm = smem;                       // [2][GBM][ASTR]
    float* Bsm = smem + 2 * GBM * ASTR;      // [2][GBK][BSTR]

    const int tid  = threadIdx.x;
    const int lane = tid & 31;
    const int warp = tid >> 5;
    const int g    = lane >> 2;
    const int t    = lane & 3;

    const int row0 = blockIdx.y * GBM;
    const int col0 = blockIdx.x * GBN;
    const int wr0  = (warp >> 1) * 32;
    const int wc0  = (warp & 1) * 64;

    const int KT = (K + GBK - 1) / GBK;

    auto issue_tile = [&](int stage, int k0) {
        float* as = Asm + stage * GBM * ASTR;
        float* bs = Bsm + stage * GBK * BSTR;
#pragma unroll
        for (int i = 0; i < 4; i++) {
            int id = tid + i * 256;
            int r  = id >> 3;
            int cc = id & 7;
            int gr = row0 + r;
            int gc = k0 + cc * 4;
            int bytes = (gr < M && gc < K) ? 16 : 0;
            const float* src = bytes ? (A + (long long)gr * K + gc) : A;
            cp_async16(as + r * ASTR + cc * 4, src, bytes);
        }
#pragma unroll
        for (int i = 0; i < 4; i++) {
            int id = tid + i * 256;
            int r  = id >> 5;
            int cc = id & 31;
            int gr = k0 + r;
            int gc = col0 + cc * 4;
            int bytes = (gr < K && gc < N) ? 16 : 0;
            const float* src = bytes ? (B + (long long)gr * N + gc) : B;
            cp_async16(bs + r * BSTR + cc * 4, src, bytes);
        }
        CP_ASYNC_COMMIT();
    };

    float acc[2][8][4];
#pragma unroll
    for (int m = 0; m < 2; m++)
#pragma unroll
        for (int n = 0; n < 8; n++)
#pragma unroll
            for (int i = 0; i < 4; i++) acc[m][n][i] = 0.f;

    issue_tile(0, 0);

    for (int it = 0; it < KT; it++) {
        const int cur = it & 1;
        if (it + 1 < KT) {
            issue_tile((it + 1) & 1, (it + 1) * GBK);
            CP_ASYNC_WAIT1();
        } else {
            CP_ASYNC_WAIT0();
        }
        __syncthreads();

        const float* as = Asm + cur * GBM * ASTR;
        const float* bs = Bsm + cur * GBK * BSTR;

#pragma unroll
        for (int kk = 0; kk < GBK / 8; kk++) {
            const int kb = kk * 8;
            unsigned a[2][4];
#pragma unroll
            for (int m = 0; m < 2; m++) {
                int r = wr0 + m * 16;
                a[m][0] = f2tf32(as[(r + g    ) * ASTR + kb + t    ]);
                a[m][1] = f2tf32(as[(r + g + 8) * ASTR + kb + t    ]);
                a[m][2] = f2tf32(as[(r + g    ) * ASTR + kb + t + 4]);
                a[m][3] = f2tf32(as[(r + g + 8) * ASTR + kb + t + 4]);
            }
#pragma unroll
            for (int n = 0; n < 8; n++) {
                int c = wc0 + n * 8 + g;
                unsigned b0 = f2tf32(bs[(kb + t    ) * BSTR + c]);
                unsigned b1 = f2tf32(bs[(kb + t + 4) * BSTR + c]);
#pragma unroll
                for (int m = 0; m < 2; m++)
                    mma_tf32(acc[m][n][0], acc[m][n][1], acc[m][n][2], acc[m][n][3],
                             a[m][0], a[m][1], a[m][2], a[m][3], b0, b1);
            }
        }
        __syncthreads();
    }

#pragma unroll
    for (int m = 0; m < 2; m++) {
#pragma unroll
        for (int n = 0; n < 8; n++) {
            int gc = col0 + wc0 + n * 8 + 2 * t;
            float bx = 0.f, by = 0.f;
            if (bias) { bx = bias[gc]; by = bias[gc + 1]; }

            int gr0 = row0 + wr0 + m * 16 + g;
            if (gr0 < M) {
                float v0 = acc[m][n][0] + bx;
                float v1 = acc[m][n][1] + by;
                if (ACT == 1) { v0 = fmaxf(v0, 0.f); v1 = fmaxf(v1, 0.f); }
                float2 v = make_float2(v0, v1);
                *reinterpret_cast<float2*>(&C[(long long)gr0 * N + gc]) = v;
                if (C2) *reinterpret_cast<float2*>(&C2[(long long)gr0 * N + gc]) = v;
            }
            int gr1 = gr0 + 8;
            if (gr1 < M) {
                float v0 = acc[m][n][2] + bx;
                float v1 = acc[m][n][3] + by;
                if (ACT == 1) { v0 = fmaxf(v0, 0.f); v1 = fmaxf(v1, 0.f); }
                float2 v = make_float2(v0, v1);
                *reinterpret_cast<float2*>(&C[(long long)gr1 * N + gc]) = v;
                if (C2) *reinterpret_cast<float2*>(&C2[(long long)gr1 * N + gc]) = v;
            }
        }
    }
}

// ---------------- weight pack -------------------------------------------------
__global__ void pack_weights_kernel(const float* __restrict__ Wf,
                                    const float* __restrict__ Ws,
                                    float* __restrict__ Wpack)
{
    int idx = blockIdx.x * 256 + threadIdx.x;
    if (idx >= 2 * 128 * 512) return;
    int l = idx >> 16;
    int k = (idx >> 9) & 127;
    int c = idx & 511;
    int sel = c >> 7;
    int j = c & 127;
    const float* W = (sel < 2) ? Wf : Ws;
    int row = (sel & 1) ? (128 + k) : k;
    Wpack[idx] = W[(long long)l * 306 * 128 + row * 128 + j];
}

// ---------------- fused edge kernel (8-edge ILP, FFMA2, smem idx, k-unroll4) --
#define TE 128
// smem: Wf 6400 + Ws 6400 + ea 6400 floats + idx 256 ints = 77824 B
#define EDGE_SMEM ((6400 + 6400 + TE * F_EDGE + 2 * TE) * 4)

__global__ __launch_bounds__(256, 2)
void edge_fused_kernel(const float* __restrict__ edge_attr,
                       const float* __restrict__ Wfe,   // [50][128]
                       const float* __restrict__ Wse,   // [50][128]
                       const float* __restrict__ bf_l,
                       const float* __restrict__ bs_l,
                       const float* __restrict__ Apack, // [N_NODES][512]
                       const int* __restrict__ src_idx,
                       const int* __restrict__ dst_idx,
                       float* __restrict__ agg)
{
    extern __shared__ float sm[];
    float* Wf_s = sm;                 // 6400 floats
    float* Ws_s = sm + 6400;          // 6400 floats
    float* ea_s = sm + 12800;         // TE*50 floats
    int*   idx_s = reinterpret_cast<int*>(sm + 12800 + TE * F_EDGE);  // [2][TE]

    const int tid  = threadIdx.x;
    const int lane = tid & 31;
    const int warp = tid >> 5;
    const int e0   = blockIdx.x * TE;

    // stage src/dst indices in smem (removes LDG from epilogue critical path)
    if (tid < TE) {
        idx_s[tid]      = src_idx[e0 + tid];
        idx_s[TE + tid] = dst_idx[e0 + tid];
    }
    // load weights (float4, coalesced)
    {
        const float4* wf4 = reinterpret_cast<const float4*>(Wfe);
        const float4* ws4 = reinterpret_cast<const float4*>(Wse);
        float4* sf4 = reinterpret_cast<float4*>(Wf_s);
        float4* ss4 = reinterpret_cast<float4*>(Ws_s);
#pragma unroll
        for (int i = 0; i < 7; i++) {
            int idx = tid + i * 256;
            if (idx < 1600) { sf4[idx] = wf4[idx]; ss4[idx] = ws4[idx]; }
        }
    }
    // load edge_attr tile
    {
        const float* gbase = edge_attr + (long long)e0 * F_EDGE;
#pragma unroll
        for (int i = 0; i < (TE * F_EDGE) / 256; i++) {
            int idx = tid + i * 256;
            ea_s[idx] = gbase[idx];
        }
    }
    __syncthreads();

    const float4 bf4 = *reinterpret_cast<const float4*>(bf_l + lane * 4);
    const float4 bs4 = *reinterpret_cast<const float4*>(bs_l + lane * 4);
    unsigned long long bf01, bf23, bs01, bs23;
    PACK_F32X2(bf01, __float_as_uint(bf4.x), __float_as_uint(bf4.y));
    PACK_F32X2(bf23, __float_as_uint(bf4.z), __float_as_uint(bf4.w));
    PACK_F32X2(bs01, __float_as_uint(bs4.x), __float_as_uint(bs4.y));
    PACK_F32X2(bs23, __float_as_uint(bs4.z), __float_as_uint(bs4.w));

    // each warp handles 16 edges, 8 at a time
#pragma unroll 1
    for (int grp = 0; grp < 2; grp++) {
        const int elb = warp * 16 + grp * 8;

        unsigned long long af01[8], af23[8], as01[8], as23[8];
#pragma unroll
        for (int q = 0; q < 8; q++) {
            af01[q] = bf01; af23[q] = bf23;
            as01[q] = bs01; as23[q] = bs23;
        }

        // k loop: 4 k's per iteration (48 k's), then a 2-k tail (k=48,49)
#pragma unroll 1
        for (int k = 0; k < 48; k += 4) {
#pragma unroll
            for (int kh = 0; kh < 2; kh++) {
                const int kb = k + kh * 2;
                const ulonglong2 wf0 = *reinterpret_cast<const ulonglong2*>(&Wf_s[kb * 128 + lane * 4]);
                const ulonglong2 ws0 = *reinterpret_cast<const ulonglong2*>(&Ws_s[kb * 128 + lane * 4]);
                const ulonglong2 wf1 = *reinterpret_cast<const ulonglong2*>(&Wf_s[(kb + 1) * 128 + lane * 4]);
                const ulonglong2 ws1 = *reinterpret_cast<const ulonglong2*>(&Ws_s[(kb + 1) * 128 + lane * 4]);

#pragma unroll
                for (int q = 0; q < 8; q++) {
                    const float2 av = *reinterpret_cast<const float2*>(&ea_s[(elb + q) * F_EDGE + kb]);
                    unsigned long long alo, ahi;
                    unsigned ulo = __float_as_uint(av.x);
                    unsigned uhi = __float_as_uint(av.y);
                    PACK_F32X2(alo, ulo, ulo);
                    PACK_F32X2(ahi, uhi, uhi);

                    FMA_F32X2(af01[q], alo, wf0.x, af01[q]);
                    FMA_F32X2(af23[q], alo, wf0.y, af23[q]);
                    FMA_F32X2(as01[q], alo, ws0.x, as01[q]);
                    FMA_F32X2(as23[q], alo, ws0.y, as23[q]);
                    FMA_F32X2(af01[q], ahi, wf1.x, af01[q]);
                    FMA_F32X2(af23[q], ahi, wf1.y, af23[q]);
                    FMA_F32X2(as01[q], ahi, ws1.x, as01[q]);
                    FMA_F32X2(as23[q], ahi, ws1.y, as23[q]);
                }
            }
        }
        {   // k tail: 48, 49
            const int kb = 48;
            const ulonglong2 wf0 = *reinterpret_cast<const ulonglong2*>(&Wf_s[kb * 128 + lane * 4]);
            const ulonglong2 ws0 = *reinterpret_cast<const ulonglong2*>(&Ws_s[kb * 128 + lane * 4]);
            const ulonglong2 wf1 = *reinterpret_cast<const ulonglong2*>(&Wf_s[(kb + 1) * 128 + lane * 4]);
            const ulonglong2 ws1 = *reinterpret_cast<const ulonglong2*>(&Ws_s[(kb + 1) * 128 + lane * 4]);
#pragma unroll
            for (int q = 0; q < 8; q++) {
                const float2 av = *reinterpret_cast<const float2*>(&ea_s[(elb + q) * F_EDGE + kb]);
                unsigned long long alo, ahi;
                unsigned ulo = __float_as_uint(av.x);
                unsigned uhi = __float_as_uint(av.y);
                PACK_F32X2(alo, ulo, ulo);
                PACK_F32X2(ahi, uhi, uhi);

                FMA_F32X2(af01[q], alo, wf0.x, af01[q]);
                FMA_F32X2(af23[q], alo, wf0.y, af23[q]);
                FMA_F32X2(as01[q], alo, ws0.x, as01[q]);
                FMA_F32X2(as23[q], alo, ws0.y, as23[q]);
                FMA_F32X2(af01[q], ahi, wf1.x, af01[q]);
                FMA_F32X2(af23[q], ahi, wf1.y, af23[q]);
                FMA_F32X2(as01[q], ahi, ws1.x, as01[q]);
                FMA_F32X2(as23[q], ahi, ws1.y, as23[q]);
            }
        }

#pragma unroll
        for (int q = 0; q < 8; q++) {
            const int el = elb + q;
            const int s = idx_s[el];
            const int d = idx_s[TE + el];

            unsigned f0u, f1u, f2u, f3u, s0u, s1u, s2u, s3u;
            UNPACK_F32X2(f0u, f1u, af01[q]);
            UNPACK_F32X2(f2u, f3u, af23[q]);
            UNPACK_F32X2(s0u, s1u, as01[q]);
            UNPACK_F32X2(s2u, s3u, as23[q]);

            const float4 afi = *reinterpret_cast<const float4*>(&Apack[(long long)d * 512 + lane * 4]);
            const float4 afj = *reinterpret_cast<const float4*>(&Apack[(long long)s * 512 + 128 + lane * 4]);
            const float4 asi = *reinterpret_cast<const float4*>(&Apack[(long long)d * 512 + 256 + lane * 4]);
            const float4 asj = *reinterpret_cast<const float4*>(&Apack[(long long)s * 512 + 384 + lane * 4]);

            float pf0 = __uint_as_float(f0u) + afi.x + afj.x;
            float pf1 = __uint_as_float(f1u) + afi.y + afj.y;
            float pf2 = __uint_as_float(f2u) + afi.z + afj.z;
            float pf3 = __uint_as_float(f3u) + afi.w + afj.w;
            float ps0 = __uint_as_float(s0u) + asi.x + asj.x;
            float ps1 = __uint_as_float(s1u) + asi.y + asj.y;
            float ps2 = __uint_as_float(s2u) + asi.z + asj.z;
            float ps3 = __uint_as_float(s3u) + asi.w + asj.w;

            float m0 = msg_fast(pf0, ps0);
            float m1 = msg_fast(pf1, ps1);
            float m2 = msg_fast(pf2, ps2);
            float m3 = msg_fast(pf3, ps3);

            float* aout = &agg[(long long)d * HID + lane * 4];
            RED_ADD_V4F32(aout, m0, m1, m2, m3);
        }
    }
}

// ---------------- launch --------------------------------------------------------
static inline void gemm_launch(int act, const float* A, const float* B,
                               const float* bias, float* C, float* C2,
                               int M, int N, int K)
{
    dim3 grid((N + GBN - 1) / GBN, (M + GBM - 1) / GBM);
    if (act == 1) gemm_tf32_kernel<1><<<grid, 256, GEMM_SMEM>>>(A, B, bias, C, C2, M, N, K);
    else          gemm_tf32_kernel<0><<<grid, 256, GEMM_SMEM>>>(A, B, bias, C, C2, M, N, K);
}

extern "C" void kernel_launch(void* const* d_in, const int* in_sizes, int n_in,
                              void* d_out, int out_size)
{
    const float* x         = (const float*)d_in[0];
    const float* edge_attr = (const float*)d_in[1];
    const float* W_in      = (const float*)d_in[2];
    const float* b_in      = (const float*)d_in[3];
    const float* Wf        = (const float*)d_in[4];
    const float* bf        = (const float*)d_in[5];
    const float* Ws        = (const float*)d_in[6];
    const float* bs        = (const float*)d_in[7];
    const float* Wm        = (const float*)d_in[8];
    const float* bm        = (const float*)d_in[9];
    const int*   ei        = (const int*)d_in[10];   // int32
    float* out = (float*)d_out;

    const int* src = ei;
    const int* dst = ei + N_EDGES;

    float* h;     cudaGetSymbolAddress((void**)&h,     g_h);
    float* Apack; cudaGetSymbolAddress((void**)&Apack, g_Apack);
    float* agg;   cudaGetSymbolAddress((void**)&agg,   g_agg);
    float* Wpack; cudaGetSymbolAddress((void**)&Wpack, g_Wpack);

    static bool smem_set = false;
    if (!smem_set) {
        cudaFuncSetAttribute(edge_fused_kernel,
                             cudaFuncAttributeMaxDynamicSharedMemorySize, EDGE_SMEM);
        cudaFuncSetAttribute(gemm_tf32_kernel<0>,
                             cudaFuncAttributeMaxDynamicSharedMemorySize, GEMM_SMEM);
        cudaFuncSetAttribute(gemm_tf32_kernel<1>,
                             cudaFuncAttributeMaxDynamicSharedMemorySize, GEMM_SMEM);
        smem_set = true;
    }

    pack_weights_kernel<<<(2 * 128 * 512 + 255) / 256, 256>>>(Wf, Ws, Wpack);

    // h = relu(x @ W_in + b_in); dual-store into agg for layer 0
    gemm_launch(1, x, W_in, b_in, h, agg, N_NODES, HID, F_NODE);

    for (int l = 0; l < 2; l++) {
        const float* Wfl = Wf + (long long)l * 306 * HID;
        const float* Wsl = Ws + (long long)l * 306 * HID;
        const float* bfl = bf + l * HID;
        const float* bsl = bs + l * HID;
        const float* Wml = Wm + (long long)l * HID * HID;
        const float* bml = bm + l * HID;
        const float* Wpl = Wpack + (long long)l * 128 * 512;

        // all 4 node projections in one GEMM: Apack = h @ Wpack_l  [50000 x 512]
        gemm_launch(0, h, Wpl, nullptr, Apack, nullptr, N_NODES, 4 * HID, HID);

        // fused: edge projection (FFMA2, 8-edge ILP) + fast message + v4 red
        edge_fused_kernel<<<N_EDGES / TE, 256, EDGE_SMEM>>>(
            edge_attr, Wfl + 256 * HID, Wsl + 256 * HID, bfl, bsl,
            Apack, src, dst, agg);

        // h = relu(agg @ Wm + bm); layer 0 dual-stores next agg; layer 1 -> out
        if (l == 0) gemm_launch(1, agg, Wml, bml, h, agg, N_NODES, HID, HID);
        else        gemm_launch(1, agg, Wml, bml, out, nullptr, N_NODES, HID, HID);
    }
}